// round 9
// baseline (speedup 1.0000x reference)
#include <cuda_runtime.h>
#include <math.h>

#define NB 8
#define SEQL 8192
#define CDIM 384
#define DH 128
#define LMK 64
#define NCH 64              // split-N chunks for kernel_3 (8192/64 = 128 keys/chunk)
#define RSCALE 0.05103103630798288f   // 1/sqrt(384)

// ---------------- device scratch (no runtime allocation) ----------------
__device__ float g_q[NB * SEQL * DH];
__device__ float g_k[NB * SEQL * DH];
__device__ float g_v[NB * SEQL * DH];
__device__ float g_qlm[NB * LMK * DH];
__device__ float g_klm[NB * LMK * DH];
__device__ float g_k2[NB * LMK * LMK];     // kernel_2 (row softmax)
__device__ float g_kinv[NB * LMK * LMK];   // Newton-Schulz pseudo-inverse
__device__ float g_ps[NB * NCH * LMK * DH];
__device__ float g_pm[NB * NCH * LMK];
__device__ float g_pz[NB * NCH * LMK];
__device__ float g_G[NB * LMK * DH];       // kinv @ (kernel_3 @ v)
__device__ float g_pwT[DH * DH];           // proj_w transposed

// ---------------- packed fp32x2 helpers (sm_100a FFMA2) ------------------
__device__ __forceinline__ void ffma2(unsigned long long& d,
                                      unsigned long long a,
                                      unsigned long long b) {
    asm("fma.rn.f32x2 %0, %1, %2, %0;" : "+l"(d) : "l"(a), "l"(b));
}
__device__ __forceinline__ void unpk2(unsigned long long p, float& lo, float& hi) {
    asm("mov.b64 {%0, %1}, %2;" : "=f"(lo), "=f"(hi) : "l"(p));
}

// =========================================================================
// 1) qkv = x @ qkv_w^T : M=65536, N=384, K=384. 128x128 tile, BK=16,
//    256 threads, 8x8 microtile, FFMA2 inner product.
//    A staged DUPLICATED in smem (As[k][2r]=As[k][2r+1]=x[r][k]) so the
//    packed-pair broadcast costs nothing in the inner loop; B pairs are
//    naturally adjacent. acc packed along j (64 regs, unchanged).
// =========================================================================
__global__ void __launch_bounds__(256) k_qkv(const float* __restrict__ x,
                                             const float* __restrict__ w) {
    __shared__ float As[16 * 264];   // duplicated A: 16.5 KB
    __shared__ float Ws[16 * 132];   // B: 8.25 KB
    const int tid = threadIdx.x;
    const int tx = tid & 15, ty = tid >> 4;
    const long row0 = (long)blockIdx.x * 128;
    const int sec = blockIdx.y;
    const int wrow0 = sec * 128;

    unsigned long long acc2[8][4];
#pragma unroll
    for (int i = 0; i < 8; i++)
#pragma unroll
        for (int j = 0; j < 4; j++) acc2[i][j] = 0ULL;

    for (int kt = 0; kt < CDIM; kt += 16) {
#pragma unroll
        for (int i = 0; i < 2; i++) {
            int p = tid + i * 256;
            int r = p >> 2, c4 = (p & 3) * 4;
            float4 a = *(const float4*)(x + (row0 + r) * CDIM + kt + c4);
            *(float2*)&As[(c4 + 0) * 264 + 2 * r] = make_float2(a.x, a.x);
            *(float2*)&As[(c4 + 1) * 264 + 2 * r] = make_float2(a.y, a.y);
            *(float2*)&As[(c4 + 2) * 264 + 2 * r] = make_float2(a.z, a.z);
            *(float2*)&As[(c4 + 3) * 264 + 2 * r] = make_float2(a.w, a.w);
            float4 b = *(const float4*)(w + (wrow0 + r) * CDIM + kt + c4);
            Ws[(c4 + 0) * 132 + r] = b.x;
            Ws[(c4 + 1) * 132 + r] = b.y;
            Ws[(c4 + 2) * 132 + r] = b.z;
            Ws[(c4 + 3) * 132 + r] = b.w;
        }
        __syncthreads();
#pragma unroll
        for (int k = 0; k < 16; k++) {
            // duplicated a-pairs: dup(a0),dup(a1) | ... | dup(a6),dup(a7)
            ulonglong2 a01 = *(const ulonglong2*)&As[k * 264 + ty * 16];
            ulonglong2 a23 = *(const ulonglong2*)&As[k * 264 + ty * 16 + 4];
            ulonglong2 a45 = *(const ulonglong2*)&As[k * 264 + ty * 16 + 8];
            ulonglong2 a67 = *(const ulonglong2*)&As[k * 264 + ty * 16 + 12];
            // natural b-pairs: (b0,b1),(b2,b3) | (b4,b5),(b6,b7)
            ulonglong2 b03 = *(const ulonglong2*)&Ws[k * 132 + tx * 8];
            ulonglong2 b47 = *(const ulonglong2*)&Ws[k * 132 + tx * 8 + 4];

            ffma2(acc2[0][0], a01.x, b03.x); ffma2(acc2[0][1], a01.x, b03.y);
            ffma2(acc2[0][2], a01.x, b47.x); ffma2(acc2[0][3], a01.x, b47.y);
            ffma2(acc2[1][0], a01.y, b03.x); ffma2(acc2[1][1], a01.y, b03.y);
            ffma2(acc2[1][2], a01.y, b47.x); ffma2(acc2[1][3], a01.y, b47.y);
            ffma2(acc2[2][0], a23.x, b03.x); ffma2(acc2[2][1], a23.x, b03.y);
            ffma2(acc2[2][2], a23.x, b47.x); ffma2(acc2[2][3], a23.x, b47.y);
            ffma2(acc2[3][0], a23.y, b03.x); ffma2(acc2[3][1], a23.y, b03.y);
            ffma2(acc2[3][2], a23.y, b47.x); ffma2(acc2[3][3], a23.y, b47.y);
            ffma2(acc2[4][0], a45.x, b03.x); ffma2(acc2[4][1], a45.x, b03.y);
            ffma2(acc2[4][2], a45.x, b47.x); ffma2(acc2[4][3], a45.x, b47.y);
            ffma2(acc2[5][0], a45.y, b03.x); ffma2(acc2[5][1], a45.y, b03.y);
            ffma2(acc2[5][2], a45.y, b47.x); ffma2(acc2[5][3], a45.y, b47.y);
            ffma2(acc2[6][0], a67.x, b03.x); ffma2(acc2[6][1], a67.x, b03.y);
            ffma2(acc2[6][2], a67.x, b47.x); ffma2(acc2[6][3], a67.x, b47.y);
            ffma2(acc2[7][0], a67.y, b03.x); ffma2(acc2[7][1], a67.y, b03.y);
            ffma2(acc2[7][2], a67.y, b47.x); ffma2(acc2[7][3], a67.y, b47.y);
        }
        __syncthreads();
    }
    float* dst = sec == 0 ? g_q : (sec == 1 ? g_k : g_v);
    const float scale = sec == 0 ? RSCALE : 1.0f;
#pragma unroll
    for (int i = 0; i < 8; i++) {
        long m = row0 + ty * 8 + i;
        float c0, c1, c2, c3, c4, c5, c6, c7;
        unpk2(acc2[i][0], c0, c1);
        unpk2(acc2[i][1], c2, c3);
        unpk2(acc2[i][2], c4, c5);
        unpk2(acc2[i][3], c6, c7);
        float4 o0, o1;
        o0.x = c0 * scale; o0.y = c1 * scale; o0.z = c2 * scale; o0.w = c3 * scale;
        o1.x = c4 * scale; o1.y = c5 * scale; o1.z = c6 * scale; o1.w = c7 * scale;
        *(float4*)&dst[m * DH + tx * 8]     = o0;
        *(float4*)&dst[m * DH + tx * 8 + 4] = o1;
    }
}

// =========================================================================
// 2) landmark means: 512 blocks (b,l), 128 threads (d). seg = 128.
// =========================================================================
__global__ void k_lm() {
    int b = blockIdx.x >> 6, l = blockIdx.x & 63;
    int d = threadIdx.x;
    const float* kp = g_k + ((long)(b * SEQL + l * 128)) * DH + d;
    const float* qp = g_q + ((long)(b * SEQL + l * 128)) * DH + d;
    float sk = 0.f, sq = 0.f;
    for (int i = 0; i < 128; i++) { sk += kp[i * DH]; sq += qp[i * DH]; }
    g_klm[(b * LMK + l) * DH + d] = sk * (1.f / 128.f);
    g_qlm[(b * LMK + l) * DH + d] = sq * (1.f / 128.f);
}

// =========================================================================
// 3) proj_w transpose (one-time, tiny)
// =========================================================================
__global__ void k_pwT(const float* __restrict__ pw) {
    int e = blockIdx.x, d = threadIdx.x;
    g_pwT[e * DH + d] = pw[d * DH + e];
}

// =========================================================================
// 64x64 matmul fragment: 4 rows x 4 cols per thread, 256 threads.
// =========================================================================
__device__ __forceinline__ void mm64(const float* Arow, const float* B,
                                     int i4, int j4, float a[4][4]) {
#pragma unroll
    for (int ii = 0; ii < 4; ii++)
#pragma unroll
        for (int jj = 0; jj < 4; jj++) a[ii][jj] = 0.f;
    for (int k = 0; k < 64; k++) {
        float4 bv = *(const float4*)&B[k * 64 + j4];
        float a0 = Arow[(i4 + 0) * 64 + k];
        float a1 = Arow[(i4 + 1) * 64 + k];
        float a2 = Arow[(i4 + 2) * 64 + k];
        float a3 = Arow[(i4 + 3) * 64 + k];
        a[0][0] += a0 * bv.x; a[0][1] += a0 * bv.y; a[0][2] += a0 * bv.z; a[0][3] += a0 * bv.w;
        a[1][0] += a1 * bv.x; a[1][1] += a1 * bv.y; a[1][2] += a1 * bv.z; a[1][3] += a1 * bv.w;
        a[2][0] += a2 * bv.x; a[2][1] += a2 * bv.y; a[2][2] += a2 * bv.z; a[2][3] += a2 * bv.w;
        a[3][0] += a3 * bv.x; a[3][1] += a3 * bv.y; a[3][2] += a3 * bv.z; a[3][3] += a3 * bv.w;
    }
}

// =========================================================================
// 4) FUSED mid-stage: grid (8, NCH+1), 256 threads, 48KB dynamic smem.
//    blockIdx.y <  NCH : kernel_3 split-N flash partial for chunk y.
//    blockIdx.y == NCH : kernel_2 softmax + Newton-Schulz inverse (batch x).
// =========================================================================
__global__ void __launch_bounds__(256) k_mid() {
    extern __shared__ float sm[];
    const int b = blockIdx.x;
    const int t = threadIdx.x;

    if (blockIdx.y == NCH) {
        float* sV = sm;            // 4096
        float* sA = sm + 4096;     // 4096
        float* sT = sm + 8192;     // 4096
        const int j4 = (t & 15) * 4;
        const int i4 = (t >> 4) * 4;

        // S = qlm @ klm^T
        {
            const float* qb = g_qlm + b * LMK * DH;
            const float* kb = g_klm + b * LMK * DH;
            float a[4][4];
#pragma unroll
            for (int ii = 0; ii < 4; ii++)
#pragma unroll
                for (int jj = 0; jj < 4; jj++) a[ii][jj] = 0.f;
            for (int d4 = 0; d4 < DH; d4 += 4) {
                float4 kv[4];
#pragma unroll
                for (int jj = 0; jj < 4; jj++)
                    kv[jj] = *(const float4*)(kb + (j4 + jj) * DH + d4);
#pragma unroll
                for (int ii = 0; ii < 4; ii++) {
                    float4 qv = *(const float4*)(qb + (i4 + ii) * DH + d4);
#pragma unroll
                    for (int jj = 0; jj < 4; jj++)
                        a[ii][jj] += qv.x*kv[jj].x + qv.y*kv[jj].y + qv.z*kv[jj].z + qv.w*kv[jj].w;
                }
            }
#pragma unroll
            for (int ii = 0; ii < 4; ii++)
#pragma unroll
                for (int jj = 0; jj < 4; jj++) sA[(i4 + ii) * 64 + j4 + jj] = a[ii][jj];
        }
        __syncthreads();
        {
            int w = t >> 5, lane = t & 31;
            for (int rr = 0; rr < 8; rr++) {
                int r = w * 8 + rr;
                float v0 = sA[r * 64 + lane], v1 = sA[r * 64 + 32 + lane];
                float m = fmaxf(v0, v1);
                for (int o = 16; o; o >>= 1) m = fmaxf(m, __shfl_xor_sync(0xffffffffu, m, o));
                v0 = __expf(v0 - m); v1 = __expf(v1 - m);
                float s = v0 + v1;
                for (int o = 16; o; o >>= 1) s += __shfl_xor_sync(0xffffffffu, s, o);
                float inv = 1.f / s;
                sA[r * 64 + lane] = v0 * inv;
                sA[r * 64 + 32 + lane] = v1 * inv;
            }
        }
        __syncthreads();
        float* Kg = g_k2 + b * 4096;
        for (int e = t; e < 4096; e += 256) Kg[e] = sA[e];
        if (t < 64) {
            float c = 0.f;
            for (int i = 0; i < 64; i++) c += sA[i * 64 + t];
            sT[t] = c;
        }
        __syncthreads();
        if (t == 0) {
            float m = sT[0];
            for (int j = 1; j < 64; j++) m = fmaxf(m, sT[j]);
            sT[0] = m;
        }
        __syncthreads();
        float rdenom = 1.f / sT[0];
        __syncthreads();
        for (int e = t; e < 4096; e += 256) {
            int i = e >> 6, j = e & 63;
            sV[e] = sA[j * 64 + i] * rdenom;
        }
        __syncthreads();

        float a[4][4];
        for (int it = 0; it < 6; it++) {
            mm64(Kg, sV, i4, j4, a);
#pragma unroll
            for (int ii = 0; ii < 4; ii++)
#pragma unroll
                for (int jj = 0; jj < 4; jj++) sA[(i4 + ii) * 64 + j4 + jj] = a[ii][jj];
            __syncthreads();
            mm64(sA, sA, i4, j4, a);
#pragma unroll
            for (int ii = 0; ii < 4; ii++)
#pragma unroll
                for (int jj = 0; jj < 4; jj++)
                    sT[(i4 + ii) * 64 + j4 + jj] = 7.f * sA[(i4 + ii) * 64 + j4 + jj] - a[ii][jj];
            __syncthreads();
            mm64(sA, sT, i4, j4, a);
#pragma unroll
            for (int ii = 0; ii < 4; ii++)
#pragma unroll
                for (int jj = 0; jj < 4; jj++)
                    a[ii][jj] = 15.f * sA[(i4 + ii) * 64 + j4 + jj] - a[ii][jj];
            __syncthreads();
#pragma unroll
            for (int ii = 0; ii < 4; ii++)
#pragma unroll
                for (int jj = 0; jj < 4; jj++) sT[(i4 + ii) * 64 + j4 + jj] = a[ii][jj];
            __syncthreads();
            mm64(sV, sT, i4, j4, a);
#pragma unroll
            for (int ii = 0; ii < 4; ii++)
#pragma unroll
                for (int jj = 0; jj < 4; jj++)
                    a[ii][jj] = 0.25f * (13.f * sV[(i4 + ii) * 64 + j4 + jj] - a[ii][jj]);
            __syncthreads();
#pragma unroll
            for (int ii = 0; ii < 4; ii++)
#pragma unroll
                for (int jj = 0; jj < 4; jj++) sV[(i4 + ii) * 64 + j4 + jj] = a[ii][jj];
            __syncthreads();
        }
        for (int e = t; e < 4096; e += 256) g_kinv[b * 4096 + e] = sV[e];
        return;
    }

    // ---------------- flash partial path (chunk c = blockIdx.y) ------------
    float* sQ   = sm;              // 8192 floats
    float* sS   = sm + 8192;       // 2048
    float* sM   = sm + 10240;      // 64
    float* sZ   = sm + 10304;      // 64
    float* sFac = sm + 10368;      // 64
    const int c = blockIdx.y;
    for (int e = t; e < LMK * DH; e += 256) sQ[e] = g_qlm[b * LMK * DH + e];
    if (t < 64) { sM[t] = -1e30f; sZ[t] = 0.f; }
    __syncthreads();

    float acc[32];
#pragma unroll
    for (int i = 0; i < 32; i++) acc[i] = 0.f;
    const int d = t & 127, half = t >> 7;
    const int jkey = t & 31, wl = (t >> 5) * 8;
    const float* kb = g_k + ((long)b * SEQL + c * 128) * DH;
    const float* vb = g_v + ((long)b * SEQL + c * 128) * DH;

    for (int tt = 0; tt < 4; tt++) {
        float s[8];
#pragma unroll
        for (int r = 0; r < 8; r++) s[r] = 0.f;
        const float* krow = kb + (tt * 32 + jkey) * DH;
        for (int d4 = 0; d4 < DH; d4 += 4) {
            float4 kv = *(const float4*)(krow + d4);
#pragma unroll
            for (int r = 0; r < 8; r++) {
                float4 qv = *(const float4*)&sQ[(wl + r) * DH + d4];
                s[r] += qv.x*kv.x + qv.y*kv.y + qv.z*kv.z + qv.w*kv.w;
            }
        }
        __syncthreads();
#pragma unroll
        for (int r = 0; r < 8; r++) {
            int l = wl + r;
            float mt = s[r];
            for (int o = 16; o; o >>= 1) mt = fmaxf(mt, __shfl_xor_sync(0xffffffffu, mt, o));
            float mold = sM[l];
            float mnew = fmaxf(mold, mt);
            float p = __expf(s[r] - mnew);
            float ps = p;
            for (int o = 16; o; o >>= 1) ps += __shfl_xor_sync(0xffffffffu, ps, o);
            if (jkey == 0) {
                float fac = __expf(mold - mnew);
                sFac[l] = fac;
                sZ[l] = sZ[l] * fac + ps;
                sM[l] = mnew;
            }
            sS[l * 32 + jkey] = p;
        }
        __syncthreads();
        const float* vt = vb + tt * 32 * DH;
#pragma unroll
        for (int la = 0; la < 32; la++) acc[la] *= sFac[half * 32 + la];
        for (int k4 = 0; k4 < 32; k4 += 4) {
            float v0 = vt[(k4 + 0) * DH + d];
            float v1 = vt[(k4 + 1) * DH + d];
            float v2 = vt[(k4 + 2) * DH + d];
            float v3 = vt[(k4 + 3) * DH + d];
#pragma unroll
            for (int la = 0; la < 32; la++) {
                float4 pv = *(float4*)&sS[(half * 32 + la) * 32 + k4];
                acc[la] += pv.x * v0 + pv.y * v1 + pv.z * v2 + pv.w * v3;
            }
        }
    }
    long base = ((long)(b * NCH + c) * LMK) * DH;
#pragma unroll
    for (int la = 0; la < 32; la++)
        g_ps[base + (half * 32 + la) * DH + d] = acc[la];
    if (t < 64) {
        g_pm[(b * NCH + c) * LMK + t] = sM[t];
        g_pz[(b * NCH + c) * LMK + t] = sZ[t];
    }
}

// =========================================================================
// 6) combine partials -> F, then G = kinv @ F. 8 blocks x 256 threads.
// =========================================================================
__global__ void __launch_bounds__(256) k_combine() {
    __shared__ float sWt[NCH * LMK];
    __shared__ float sF[LMK * DH];
    const int b = blockIdx.x, t = threadIdx.x;
    if (t < 64) {
        int l = t;
        float M = -1e30f;
        for (int c = 0; c < NCH; c++) M = fmaxf(M, g_pm[(b * NCH + c) * LMK + l]);
        float Z = 0.f;
        for (int c = 0; c < NCH; c++)
            Z += g_pz[(b * NCH + c) * LMK + l] * __expf(g_pm[(b * NCH + c) * LMK + l] - M);
        float rZ = 1.f / Z;
        for (int c = 0; c < NCH; c++)
            sWt[c * LMK + l] = __expf(g_pm[(b * NCH + c) * LMK + l] - M) * rZ;
    }
    __syncthreads();
    const int d = t & 127, half = t >> 7;
    for (int la = 0; la < 32; la++) {
        int l = half * 32 + la;
        float acc = 0.f;
        for (int c = 0; c < NCH; c++)
            acc += g_ps[(((long)(b * NCH + c)) * LMK + l) * DH + d] * sWt[c * LMK + l];
        sF[l * DH + d] = acc;
    }
    __syncthreads();
    const float* inv = g_kinv + b * 4096;
    for (int la = 0; la < 32; la++) {
        int l = half * 32 + la;
        float acc = 0.f;
        for (int j = 0; j < 64; j++) acc += inv[l * 64 + j] * sF[j * DH + d];
        g_G[((long)b * LMK + l) * DH + d] = acc;
    }
}

// =========================================================================
// 7) fused epilogue: kernel_1 softmax -> @G -> proj -> +bias -> +v residual.
// =========================================================================
__global__ void __launch_bounds__(256) k_out(const float* __restrict__ pb,
                                             float* __restrict__ out) {
    __shared__ float sQ[LMK * DH];   // q tile, later reused for o
    __shared__ float sP[LMK * LMK];
    const int bid = blockIdx.x;
    const int b = bid >> 7;
    const int n0 = (bid & 127) * 64;
    const int t = threadIdx.x;
    const long rowbase = (long)b * SEQL + n0;

    for (int e = t; e < LMK * DH; e += 256) sQ[e] = g_q[rowbase * DH + e];
    __syncthreads();
    {
        const int l = t & 63, rg = t >> 6;
        const float* krow = g_klm + ((long)b * LMK + l) * DH;
        float s[16];
#pragma unroll
        for (int r = 0; r < 16; r++) s[r] = 0.f;
        for (int d4 = 0; d4 < DH; d4 += 4) {
            float4 kv = *(const float4*)(krow + d4);
#pragma unroll
            for (int r = 0; r < 16; r++) {
                float4 qv = *(const float4*)&sQ[(rg * 16 + r) * DH + d4];
                s[r] += qv.x*kv.x + qv.y*kv.y + qv.z*kv.z + qv.w*kv.w;
            }
        }
#pragma unroll
        for (int r = 0; r < 16; r++) sP[(rg * 16 + r) * 64 + l] = s[r];
    }
    __syncthreads();
    {
        const int w = t >> 5, lane = t & 31;
        for (int rr = 0; rr < 8; rr++) {
            int r = w * 8 + rr;
            float v0 = sP[r * 64 + lane], v1 = sP[r * 64 + 32 + lane];
            float m = fmaxf(v0, v1);
            for (int o = 16; o; o >>= 1) m = fmaxf(m, __shfl_xor_sync(0xffffffffu, m, o));
            v0 = __expf(v0 - m); v1 = __expf(v1 - m);
            float s = v0 + v1;
            for (int o = 16; o; o >>= 1) s += __shfl_xor_sync(0xffffffffu, s, o);
            float inv = 1.f / s;
            sP[r * 64 + lane] = v0 * inv;
            sP[r * 64 + 32 + lane] = v1 * inv;
        }
    }
    __syncthreads();
    const int d = t & 127, half = t >> 7;
    float o[32];
#pragma unroll
    for (int la = 0; la < 32; la++) o[la] = 0.f;
    const float* Gb = g_G + (long)b * LMK * DH;
    for (int l4 = 0; l4 < 64; l4 += 4) {
        float g0 = Gb[(l4 + 0) * DH + d];
        float g1 = Gb[(l4 + 1) * DH + d];
        float g2 = Gb[(l4 + 2) * DH + d];
        float g3 = Gb[(l4 + 3) * DH + d];
#pragma unroll
        for (int la = 0; la < 32; la++) {
            float4 pv = *(float4*)&sP[(half * 32 + la) * 64 + l4];
            o[la] += pv.x * g0 + pv.y * g1 + pv.z * g2 + pv.w * g3;
        }
    }
    __syncthreads();
#pragma unroll
    for (int la = 0; la < 32; la++) sQ[(half * 32 + la) * DH + d] = o[la];
    __syncthreads();
    float y[32];
#pragma unroll
    for (int la = 0; la < 32; la++) y[la] = 0.f;
    for (int e4 = 0; e4 < DH; e4 += 4) {
        float w0 = g_pwT[(e4 + 0) * DH + d];
        float w1 = g_pwT[(e4 + 1) * DH + d];
        float w2 = g_pwT[(e4 + 2) * DH + d];
        float w3 = g_pwT[(e4 + 3) * DH + d];
#pragma unroll
        for (int la = 0; la < 32; la++) {
            float4 ov = *(float4*)&sQ[(half * 32 + la) * DH + e4];
            y[la] += ov.x * w0 + ov.y * w1 + ov.z * w2 + ov.w * w3;
        }
    }
    const float bias = pb[d];
#pragma unroll
    for (int la = 0; la < 32; la++) {
        long n = rowbase + half * 32 + la;
        out[n * DH + d] = g_v[n * DH + d] + y[la] + bias;
    }
}

// =========================================================================
extern "C" void kernel_launch(void* const* d_in, const int* in_sizes, int n_in,
                              void* d_out, int out_size) {
    const float* x      = (const float*)d_in[0];
    const float* qkv_w  = (const float*)d_in[1];
    const float* proj_w = (const float*)d_in[2];
    const float* proj_b = (const float*)d_in[3];
    float* out = (float*)d_out;

    k_qkv<<<dim3(512, 3), 256>>>(x, qkv_w);
    k_lm<<<512, 128>>>();
    k_pwT<<<128, 128>>>(proj_w);
    k_mid<<<dim3(8, NCH + 1), 256, 49152>>>();
    k_combine<<<8, 256>>>();
    k_out<<<1024, 256>>>(proj_b, out);
}

// round 14
// speedup vs baseline: 1.3137x; 1.3137x over previous
#include <cuda_runtime.h>
#include <cuda_bf16.h>
#include <stdint.h>
#include <math.h>

typedef unsigned int u32;

#define NB 8
#define SEQL 8192
#define CDIM 384
#define DH 128
#define LMK 64
#define NCH 64
#define RSCALE 0.05103103630798288f
#define SKEW 24

// ---------------- device scratch (no runtime allocation) ----------------
__device__ float g_q[NB * SEQL * DH];
__device__ float g_k[NB * SEQL * DH];
__device__ float g_v[NB * SEQL * DH];
__device__ float g_qlm[NB * LMK * DH];
__device__ float g_klm[NB * LMK * DH];
__device__ float g_k2[NB * LMK * LMK];
__device__ float g_kinv[NB * LMK * LMK];
__device__ float g_ps[NB * NCH * LMK * DH];
__device__ float g_pm[NB * NCH * LMK];
__device__ float g_pz[NB * NCH * LMK];
__device__ float g_G[NB * LMK * DH];
__device__ float g_pwT[DH * DH];

// =========================================================================
// landmark means: 512 blocks (b,l), 128 threads (d). seg = 128.
// =========================================================================
__global__ void k_lm() {
    int b = blockIdx.x >> 6, l = blockIdx.x & 63;
    int d = threadIdx.x;
    const float* kp = g_k + ((long)(b * SEQL + l * 128)) * DH + d;
    const float* qp = g_q + ((long)(b * SEQL + l * 128)) * DH + d;
    float sk = 0.f, sq = 0.f;
    for (int i = 0; i < 128; i++) { sk += kp[i * DH]; sq += qp[i * DH]; }
    g_klm[(b * LMK + l) * DH + d] = sk * (1.f / 128.f);
    g_qlm[(b * LMK + l) * DH + d] = sq * (1.f / 128.f);
}

// =========================================================================
// proj_w transpose (one-time, tiny)
// =========================================================================
__global__ void k_pwT(const float* __restrict__ pw) {
    int e = blockIdx.x, d = threadIdx.x;
    g_pwT[e * DH + d] = pw[d * DH + e];
}

// =========================================================================
// 64x64 matmul fragment: 4 rows x 4 cols per thread, 256 threads.
// =========================================================================
__device__ __forceinline__ void mm64(const float* Arow, const float* B,
                                     int i4, int j4, float a[4][4]) {
#pragma unroll
    for (int ii = 0; ii < 4; ii++)
#pragma unroll
        for (int jj = 0; jj < 4; jj++) a[ii][jj] = 0.f;
    for (int k = 0; k < 64; k++) {
        float4 bv = *(const float4*)&B[k * 64 + j4];
        float a0 = Arow[(i4 + 0) * 64 + k];
        float a1 = Arow[(i4 + 1) * 64 + k];
        float a2 = Arow[(i4 + 2) * 64 + k];
        float a3 = Arow[(i4 + 3) * 64 + k];
        a[0][0] += a0 * bv.x; a[0][1] += a0 * bv.y; a[0][2] += a0 * bv.z; a[0][3] += a0 * bv.w;
        a[1][0] += a1 * bv.x; a[1][1] += a1 * bv.y; a[1][2] += a1 * bv.z; a[1][3] += a1 * bv.w;
        a[2][0] += a2 * bv.x; a[2][1] += a2 * bv.y; a[2][2] += a2 * bv.z; a[2][3] += a2 * bv.w;
        a[3][0] += a3 * bv.x; a[3][1] += a3 * bv.y; a[3][2] += a3 * bv.z; a[3][3] += a3 * bv.w;
    }
}

// =========================================================================
// FUSED mid-stage: grid (8, NCH+1), 256 threads, 48KB dynamic smem.
// blockIdx.y < NCH: flash partial; == NCH: softmax + Newton-Schulz inverse.
// =========================================================================
__global__ void __launch_bounds__(256) k_mid() {
    extern __shared__ float sm[];
    const int b = blockIdx.x;
    const int t = threadIdx.x;

    if (blockIdx.y == NCH) {
        float* sV = sm;
        float* sA = sm + 4096;
        float* sT = sm + 8192;
        const int j4 = (t & 15) * 4;
        const int i4 = (t >> 4) * 4;

        // S = qlm @ klm^T
        const float* qb = g_qlm + b * LMK * DH;
        const float* kb = g_klm + b * LMK * DH;
        float a[4][4];
#pragma unroll
        for (int ii = 0; ii < 4; ii++)
#pragma unroll
            for (int jj = 0; jj < 4; jj++) a[ii][jj] = 0.f;
        for (int d4 = 0; d4 < DH; d4 += 4) {
            float4 kv[4];
#pragma unroll
            for (int jj = 0; jj < 4; jj++)
                kv[jj] = *(const float4*)(kb + (j4 + jj) * DH + d4);
#pragma unroll
            for (int ii = 0; ii < 4; ii++) {
                float4 qv = *(const float4*)(qb + (i4 + ii) * DH + d4);
#pragma unroll
                for (int jj = 0; jj < 4; jj++)
                    a[ii][jj] += qv.x*kv[jj].x + qv.y*kv[jj].y + qv.z*kv[jj].z + qv.w*kv[jj].w;
            }
        }
#pragma unroll
        for (int ii = 0; ii < 4; ii++)
#pragma unroll
            for (int jj = 0; jj < 4; jj++) sA[(i4 + ii) * 64 + j4 + jj] = a[ii][jj];
        __syncthreads();
        // row softmax: 8 warps x 8 rows
        const int sw = t >> 5;
        const int slane = t & 31;
        for (int rr = 0; rr < 8; rr++) {
            int r = sw * 8 + rr;
            float v0 = sA[r * 64 + slane], v1 = sA[r * 64 + 32 + slane];
            float m = fmaxf(v0, v1);
            for (int o = 16; o; o >>= 1) m = fmaxf(m, __shfl_xor_sync(0xffffffffu, m, o));
            v0 = __expf(v0 - m); v1 = __expf(v1 - m);
            float s = v0 + v1;
            for (int o = 16; o; o >>= 1) s += __shfl_xor_sync(0xffffffffu, s, o);
            float inv = 1.f / s;
            sA[r * 64 + slane] = v0 * inv;
            sA[r * 64 + 32 + slane] = v1 * inv;
        }
        __syncthreads();
        float* Kg = g_k2 + b * 4096;
        for (int e = t; e < 4096; e += 256) Kg[e] = sA[e];
        if (t < 64) {
            float csum = 0.f;
            for (int i = 0; i < 64; i++) csum += sA[i * 64 + t];
            sT[t] = csum;
        }
        __syncthreads();
        if (t == 0) {
            float m = sT[0];
            for (int j = 1; j < 64; j++) m = fmaxf(m, sT[j]);
            sT[0] = m;
        }
        __syncthreads();
        float rdenom = 1.f / sT[0];
        __syncthreads();
        for (int e = t; e < 4096; e += 256) {
            int i = e >> 6, j = e & 63;
            sV[e] = sA[j * 64 + i] * rdenom;
        }
        __syncthreads();

        for (int it = 0; it < 6; it++) {
            mm64(Kg, sV, i4, j4, a);
#pragma unroll
            for (int ii = 0; ii < 4; ii++)
#pragma unroll
                for (int jj = 0; jj < 4; jj++) sA[(i4 + ii) * 64 + j4 + jj] = a[ii][jj];
            __syncthreads();
            mm64(sA, sA, i4, j4, a);
#pragma unroll
            for (int ii = 0; ii < 4; ii++)
#pragma unroll
                for (int jj = 0; jj < 4; jj++)
                    sT[(i4 + ii) * 64 + j4 + jj] = 7.f * sA[(i4 + ii) * 64 + j4 + jj] - a[ii][jj];
            __syncthreads();
            mm64(sA, sT, i4, j4, a);
#pragma unroll
            for (int ii = 0; ii < 4; ii++)
#pragma unroll
                for (int jj = 0; jj < 4; jj++)
                    a[ii][jj] = 15.f * sA[(i4 + ii) * 64 + j4 + jj] - a[ii][jj];
            __syncthreads();
#pragma unroll
            for (int ii = 0; ii < 4; ii++)
#pragma unroll
                for (int jj = 0; jj < 4; jj++) sT[(i4 + ii) * 64 + j4 + jj] = a[ii][jj];
            __syncthreads();
            mm64(sV, sT, i4, j4, a);
#pragma unroll
            for (int ii = 0; ii < 4; ii++)
#pragma unroll
                for (int jj = 0; jj < 4; jj++)
                    a[ii][jj] = 0.25f * (13.f * sV[(i4 + ii) * 64 + j4 + jj] - a[ii][jj]);
            __syncthreads();
#pragma unroll
            for (int ii = 0; ii < 4; ii++)
#pragma unroll
                for (int jj = 0; jj < 4; jj++) sV[(i4 + ii) * 64 + j4 + jj] = a[ii][jj];
            __syncthreads();
        }
        for (int e = t; e < 4096; e += 256) g_kinv[b * 4096 + e] = sV[e];
        return;
    }

    // ---------------- flash partial path (chunk c = blockIdx.y) ------------
    float* sQ   = sm;
    float* sS   = sm + 8192;
    float* sM   = sm + 10240;
    float* sZ   = sm + 10304;
    float* sFac = sm + 10368;
    const int c = blockIdx.y;
    for (int e = t; e < LMK * DH; e += 256) sQ[e] = g_qlm[b * LMK * DH + e];
    if (t < 64) { sM[t] = -1e30f; sZ[t] = 0.f; }
    __syncthreads();

    float acc[32];
#pragma unroll
    for (int i = 0; i < 32; i++) acc[i] = 0.f;
    const int d = t & 127;
    const int hf = t >> 7;
    const int jkey = t & 31;
    const int wl = (t >> 5) * 8;
    const float* kb = g_k + ((long)b * SEQL + c * 128) * DH;
    const float* vb = g_v + ((long)b * SEQL + c * 128) * DH;

    for (int tt = 0; tt < 4; tt++) {
        float s[8];
#pragma unroll
        for (int r = 0; r < 8; r++) s[r] = 0.f;
        const float* krow = kb + (tt * 32 + jkey) * DH;
        for (int d4 = 0; d4 < DH; d4 += 4) {
            float4 kv = *(const float4*)(krow + d4);
#pragma unroll
            for (int r = 0; r < 8; r++) {
                float4 qv = *(const float4*)&sQ[(wl + r) * DH + d4];
                s[r] += qv.x*kv.x + qv.y*kv.y + qv.z*kv.z + qv.w*kv.w;
            }
        }
        __syncthreads();
#pragma unroll
        for (int r = 0; r < 8; r++) {
            int l = wl + r;
            float mt = s[r];
            for (int o = 16; o; o >>= 1) mt = fmaxf(mt, __shfl_xor_sync(0xffffffffu, mt, o));
            float mold = sM[l];
            float mnew = fmaxf(mold, mt);
            float p = __expf(s[r] - mnew);
            float ps = p;
            for (int o = 16; o; o >>= 1) ps += __shfl_xor_sync(0xffffffffu, ps, o);
            if (jkey == 0) {
                float fac = __expf(mold - mnew);
                sFac[l] = fac;
                sZ[l] = sZ[l] * fac + ps;
                sM[l] = mnew;
            }
            sS[l * 32 + jkey] = p;
        }
        __syncthreads();
        const float* vt = vb + tt * 32 * DH;
#pragma unroll
        for (int la = 0; la < 32; la++) acc[la] *= sFac[hf * 32 + la];
        for (int k4 = 0; k4 < 32; k4 += 4) {
            float v0 = vt[(k4 + 0) * DH + d];
            float v1 = vt[(k4 + 1) * DH + d];
            float v2 = vt[(k4 + 2) * DH + d];
            float v3 = vt[(k4 + 3) * DH + d];
#pragma unroll
            for (int la = 0; la < 32; la++) {
                float4 pv = *(float4*)&sS[(hf * 32 + la) * 32 + k4];
                acc[la] += pv.x * v0 + pv.y * v1 + pv.z * v2 + pv.w * v3;
            }
        }
    }
    long base = ((long)(b * NCH + c) * LMK) * DH;
#pragma unroll
    for (int la = 0; la < 32; la++)
        g_ps[base + (hf * 32 + la) * DH + d] = acc[la];
    if (t < 64) {
        g_pm[(b * NCH + c) * LMK + t] = sM[t];
        g_pz[(b * NCH + c) * LMK + t] = sZ[t];
    }
}

// =========================================================================
// combine partials -> F, then G = kinv @ F. 8 blocks x 256 threads.
// =========================================================================
__global__ void __launch_bounds__(256) k_combine() {
    __shared__ float sWt[NCH * LMK];
    __shared__ float sF[LMK * DH];
    const int b = blockIdx.x, t = threadIdx.x;
    if (t < 64) {
        int l = t;
        float M = -1e30f;
        for (int c = 0; c < NCH; c++) M = fmaxf(M, g_pm[(b * NCH + c) * LMK + l]);
        float Z = 0.f;
        for (int c = 0; c < NCH; c++)
            Z += g_pz[(b * NCH + c) * LMK + l] * __expf(g_pm[(b * NCH + c) * LMK + l] - M);
        float rZ = 1.f / Z;
        for (int c = 0; c < NCH; c++)
            sWt[c * LMK + l] = __expf(g_pm[(b * NCH + c) * LMK + l] - M) * rZ;
    }
    __syncthreads();
    const int d = t & 127;
    const int hf = t >> 7;
    for (int la = 0; la < 32; la++) {
        int l = hf * 32 + la;
        float acc = 0.f;
        for (int c = 0; c < NCH; c++)
            acc += g_ps[(((long)(b * NCH + c)) * LMK + l) * DH + d] * sWt[c * LMK + l];
        sF[l * DH + d] = acc;
    }
    __syncthreads();
    const float* inv = g_kinv + b * 4096;
    for (int la = 0; la < 32; la++) {
        int l = hf * 32 + la;
        float acc = 0.f;
        for (int j = 0; j < 64; j++) acc += inv[l * 64 + j] * sF[j * DH + d];
        g_G[((long)b * LMK + l) * DH + d] = acc;
    }
}

// =========================================================================
// fused epilogue: kernel_1 softmax -> @G -> proj -> +bias -> +v residual.
// =========================================================================
__global__ void __launch_bounds__(256) k_out(const float* __restrict__ pb,
                                             float* __restrict__ out) {
    __shared__ float sQ[LMK * DH];
    __shared__ float sP[LMK * LMK];
    const int bid = blockIdx.x;
    const int b = bid >> 7;
    const int n0 = (bid & 127) * 64;
    const int t = threadIdx.x;
    const long rowbase = (long)b * SEQL + n0;

    for (int e = t; e < LMK * DH; e += 256) sQ[e] = g_q[rowbase * DH + e];
    __syncthreads();
    const int sl = t & 63;
    const int rg = t >> 6;
    const float* krow = g_klm + ((long)b * LMK + sl) * DH;
    float s[16];
#pragma unroll
    for (int r = 0; r < 16; r++) s[r] = 0.f;
    for (int d4 = 0; d4 < DH; d4 += 4) {
        float4 kv = *(const float4*)(krow + d4);
#pragma unroll
        for (int r = 0; r < 16; r++) {
            float4 qv = *(const float4*)&sQ[(rg * 16 + r) * DH + d4];
            s[r] += qv.x*kv.x + qv.y*kv.y + qv.z*kv.z + qv.w*kv.w;
        }
    }
#pragma unroll
    for (int r = 0; r < 16; r++) sP[(rg * 16 + r) * 64 + sl] = s[r];
    __syncthreads();
    const int sw = t >> 5;
    const int slane = t & 31;
    for (int rr = 0; rr < 8; rr++) {
        int r = sw * 8 + rr;
        float v0 = sP[r * 64 + slane], v1 = sP[r * 64 + 32 + slane];
        float m = fmaxf(v0, v1);
        for (int o = 16; o; o >>= 1) m = fmaxf(m, __shfl_xor_sync(0xffffffffu, m, o));
        v0 = __expf(v0 - m); v1 = __expf(v1 - m);
        float ssum = v0 + v1;
        for (int o = 16; o; o >>= 1) ssum += __shfl_xor_sync(0xffffffffu, ssum, o);
        float inv = 1.f / ssum;
        sP[r * 64 + slane] = v0 * inv;
        sP[r * 64 + 32 + slane] = v1 * inv;
    }
    __syncthreads();
    const int d = t & 127;
    const int hf = t >> 7;
    float o[32];
#pragma unroll
    for (int la = 0; la < 32; la++) o[la] = 0.f;
    const float* Gb = g_G + (long)b * LMK * DH;
    for (int l4 = 0; l4 < 64; l4 += 4) {
        float g0 = Gb[(l4 + 0) * DH + d];
        float g1 = Gb[(l4 + 1) * DH + d];
        float g2 = Gb[(l4 + 2) * DH + d];
        float g3 = Gb[(l4 + 3) * DH + d];
#pragma unroll
        for (int la = 0; la < 32; la++) {
            float4 pv = *(float4*)&sP[(hf * 32 + la) * 64 + l4];
            o[la] += pv.x * g0 + pv.y * g1 + pv.z * g2 + pv.w * g3;
        }
    }
    __syncthreads();
#pragma unroll
    for (int la = 0; la < 32; la++) sQ[(hf * 32 + la) * DH + d] = o[la];
    __syncthreads();
    float y[32];
#pragma unroll
    for (int la = 0; la < 32; la++) y[la] = 0.f;
    for (int e4 = 0; e4 < DH; e4 += 4) {
        float w0 = g_pwT[(e4 + 0) * DH + d];
        float w1 = g_pwT[(e4 + 1) * DH + d];
        float w2 = g_pwT[(e4 + 2) * DH + d];
        float w3 = g_pwT[(e4 + 3) * DH + d];
#pragma unroll
        for (int la = 0; la < 32; la++) {
            float4 ov = *(float4*)&sQ[(hf * 32 + la) * DH + e4];
            y[la] += ov.x * w0 + ov.y * w1 + ov.z * w2 + ov.w * w3;
        }
    }
    const float bias = pb[d];
#pragma unroll
    for (int la = 0; la < 32; la++) {
        long n = rowbase + hf * 32 + la;
        out[n * DH + d] = g_v[n * DH + d] + y[la] + bias;
    }
}

// ---------------- mma.sync helpers (header-independent u32) ---------------
__device__ __forceinline__ void ldsm4(u32& r0, u32& r1, u32& r2, u32& r3, u32 addr) {
    asm volatile("ldmatrix.sync.aligned.m8n8.x4.shared.b16 {%0,%1,%2,%3}, [%4];" : "=r"(r0), "=r"(r1), "=r"(r2), "=r"(r3) : "r"(addr));
}
__device__ __forceinline__ void mma16816(float* d, const u32* a, const u32* b) {
    asm volatile("mma.sync.aligned.m16n8k16.row.col.f32.bf16.bf16.f32 {%0,%1,%2,%3}, {%4,%5,%6,%7}, {%8,%9}, {%0,%1,%2,%3};" : "+f"(d[0]), "+f"(d[1]), "+f"(d[2]), "+f"(d[3]) : "r"(a[0]), "r"(a[1]), "r"(a[2]), "r"(a[3]), "r"(b[0]), "r"(b[1]));
}
__device__ __forceinline__ u32 pk2(__nv_bfloat16 a, __nv_bfloat16 b) {
    return (u32)__bfloat16_as_ushort(a) | ((u32)__bfloat16_as_ushort(b) << 16);
}
__device__ __forceinline__ void bsplit(float v, __nv_bfloat16& h, __nv_bfloat16& l) {
    h = __float2bfloat16(v);
    l = __float2bfloat16(v - __bfloat162float(h));
}

// =========================================================================
// qkv = x @ qkv_w^T via bf16-split tensor-core mma (hh + hl + lh).
// grid (512, 3), 512 thr = 16 warps (4x4), warp tile 32x32, BK=16.
// =========================================================================
__global__ void __launch_bounds__(512) k_qkv(const float* __restrict__ x,
                                             const float* __restrict__ w) {
    __shared__ __align__(16) __nv_bfloat16 Ah[128 * SKEW];
    __shared__ __align__(16) __nv_bfloat16 Al[128 * SKEW];
    __shared__ __align__(16) __nv_bfloat16 Bh[128 * SKEW];
    __shared__ __align__(16) __nv_bfloat16 Bl[128 * SKEW];

    const int tid = threadIdx.x;
    const int wid = tid >> 5;
    const int lane = tid & 31;
    const long row0 = (long)blockIdx.x * 128;
    const int sec = blockIdx.y;
    const int wrow0 = sec * 128;
    const int wm = (wid >> 2) * 32;
    const int wn = (wid & 3) * 32;
    const int srow = tid >> 2;
    const int sc4 = (tid & 3) * 4;

    float acc[2][4][4];
#pragma unroll
    for (int i = 0; i < 2; i++)
#pragma unroll
        for (int j = 0; j < 4; j++)
#pragma unroll
            for (int e = 0; e < 4; e++) acc[i][j][e] = 0.f;

    const u32 baseAh = (u32)__cvta_generic_to_shared(Ah);
    const u32 baseAl = (u32)__cvta_generic_to_shared(Al);
    const u32 baseBh = (u32)__cvta_generic_to_shared(Bh);
    const u32 baseBl = (u32)__cvta_generic_to_shared(Bl);
    const int arow = (lane & 7) + ((lane >> 3) & 1) * 8;
    const int acol = (lane >> 4) * 8;
    const int bmm = lane >> 3;
    const int brow = (bmm >> 1) * 8 + (lane & 7);
    const int bcol = (bmm & 1) * 8;

    for (int kt = 0; kt < CDIM; kt += 16) {
        // stage: f32 -> (hi,lo) bf16, k-major rows with SKEW
        float4 av = *(const float4*)(x + (row0 + srow) * CDIM + kt + sc4);
        __nv_bfloat16 h0, h1, h2, h3, l0, l1, l2, l3;
        bsplit(av.x, h0, l0);
        bsplit(av.y, h1, l1);
        bsplit(av.z, h2, l2);
        bsplit(av.w, h3, l3);
        *(uint2*)(Ah + srow * SKEW + sc4) = make_uint2(pk2(h0, h1), pk2(h2, h3));
        *(uint2*)(Al + srow * SKEW + sc4) = make_uint2(pk2(l0, l1), pk2(l2, l3));
        float4 bv = *(const float4*)(w + (wrow0 + srow) * CDIM + kt + sc4);
        bsplit(bv.x, h0, l0);
        bsplit(bv.y, h1, l1);
        bsplit(bv.z, h2, l2);
        bsplit(bv.w, h3, l3);
        *(uint2*)(Bh + srow * SKEW + sc4) = make_uint2(pk2(h0, h1), pk2(h2, h3));
        *(uint2*)(Bl + srow * SKEW + sc4) = make_uint2(pk2(l0, l1), pk2(l2, l3));
        __syncthreads();

        u32 ah[2][4];
        u32 al[2][4];
        u32 bh[4][2];
        u32 bl[4][2];
#pragma unroll
        for (int mt = 0; mt < 2; mt++) {
            u32 ao = (u32)((wm + mt * 16 + arow) * SKEW + acol) * 2u;
            ldsm4(ah[mt][0], ah[mt][1], ah[mt][2], ah[mt][3], baseAh + ao);
            ldsm4(al[mt][0], al[mt][1], al[mt][2], al[mt][3], baseAl + ao);
        }
#pragma unroll
        for (int p = 0; p < 2; p++) {
            u32 bo = (u32)((wn + p * 16 + brow) * SKEW + bcol) * 2u;
            ldsm4(bh[p * 2][0], bh[p * 2][1], bh[p * 2 + 1][0], bh[p * 2 + 1][1], baseBh + bo);
            ldsm4(bl[p * 2][0], bl[p * 2][1], bl[p * 2 + 1][0], bl[p * 2 + 1][1], baseBl + bo);
        }
#pragma unroll
        for (int mt = 0; mt < 2; mt++)
#pragma unroll
            for (int nt = 0; nt < 4; nt++) {
                mma16816(acc[mt][nt], ah[mt], bh[nt]);
                mma16816(acc[mt][nt], ah[mt], bl[nt]);
                mma16816(acc[mt][nt], al[mt], bh[nt]);
            }
        __syncthreads();
    }

    float* dst = sec == 0 ? g_q : (sec == 1 ? g_k : g_v);
    const float scale = sec == 0 ? RSCALE : 1.0f;
    const int grp = lane >> 2;
    const int qd = lane & 3;
#pragma unroll
    for (int mt = 0; mt < 2; mt++)
#pragma unroll
        for (int nt = 0; nt < 4; nt++) {
            long m0 = row0 + wm + mt * 16 + grp;
            int col = wn + nt * 8 + qd * 2;
            *(float2*)&dst[m0 * DH + col] = make_float2(acc[mt][nt][0] * scale, acc[mt][nt][1] * scale);
            *(float2*)&dst[(m0 + 8) * DH + col] = make_float2(acc[mt][nt][2] * scale, acc[mt][nt][3] * scale);
        }
}

// =========================================================================
extern "C" void kernel_launch(void* const* d_in, const int* in_sizes, int n_in,
                              void* d_out, int out_size) {
    const float* x      = (const float*)d_in[0];
    const float* qkv_w  = (const float*)d_in[1];
    const float* proj_w = (const float*)d_in[2];
    const float* proj_b = (const float*)d_in[3];
    float* out = (float*)d_out;

    k_qkv<<<dim3(512, 3), 512>>>(x, qkv_w);
    k_lm<<<512, 128>>>();
    k_pwT<<<128, 128>>>(proj_w);
    k_mid<<<dim3(8, NCH + 1), 256, 49152>>>();
    k_combine<<<8, 256>>>();
    k_out<<<1024, 256>>>(proj_b, out);
}

// round 16
// speedup vs baseline: 1.3646x; 1.0387x over previous
#include <cuda_runtime.h>
#include <cuda_bf16.h>
#include <stdint.h>
#include <math.h>

typedef unsigned int u32;

#define NB 8
#define SEQL 8192
#define CDIM 384
#define DH 128
#define LMK 64
#define NCH 64
#define RSCALE 0.05103103630798288f
#define SKEW 24

// ---------------- device scratch (no runtime allocation) ----------------
__device__ float g_q[NB * SEQL * DH];
__device__ float g_k[NB * SEQL * DH];
__device__ float g_v[NB * SEQL * DH];
__device__ float g_qlm[NB * LMK * DH];
__device__ float g_klm[NB * LMK * DH];
__device__ float g_k2[NB * LMK * LMK];
__device__ float g_kinv[NB * LMK * LMK];
__device__ float g_ps[NB * NCH * LMK * DH];
__device__ float g_pm[NB * NCH * LMK];
__device__ float g_pz[NB * NCH * LMK];
__device__ float g_G[NB * LMK * DH];
__device__ float g_pwT[DH * DH];
// bf16 hi/lo precomputed operands for the tensor-core QKV GEMM
__device__ __nv_bfloat16 g_xh[NB * SEQL * CDIM];
__device__ __nv_bfloat16 g_xl[NB * SEQL * CDIM];
__device__ __nv_bfloat16 g_wh[3 * DH * CDIM];
__device__ __nv_bfloat16 g_wl[3 * DH * CDIM];

// =========================================================================
// landmark means: 512 blocks (b,l), 128 threads (d). seg = 128.
// =========================================================================
__global__ void k_lm() {
    int b = blockIdx.x >> 6, l = blockIdx.x & 63;
    int d = threadIdx.x;
    const float* kp = g_k + ((long)(b * SEQL + l * 128)) * DH + d;
    const float* qp = g_q + ((long)(b * SEQL + l * 128)) * DH + d;
    float sk = 0.f, sq = 0.f;
    for (int i = 0; i < 128; i++) { sk += kp[i * DH]; sq += qp[i * DH]; }
    g_klm[(b * LMK + l) * DH + d] = sk * (1.f / 128.f);
    g_qlm[(b * LMK + l) * DH + d] = sq * (1.f / 128.f);
}

// =========================================================================
// proj_w transpose (one-time, tiny)
// =========================================================================
__global__ void k_pwT(const float* __restrict__ pw) {
    int e = blockIdx.x, d = threadIdx.x;
    g_pwT[e * DH + d] = pw[d * DH + e];
}

// =========================================================================
// 64x64 matmul fragment: 4 rows x 4 cols per thread, 256 threads.
// =========================================================================
__device__ __forceinline__ void mm64(const float* Arow, const float* B,
                                     int i4, int j4, float a[4][4]) {
#pragma unroll
    for (int ii = 0; ii < 4; ii++)
#pragma unroll
        for (int jj = 0; jj < 4; jj++) a[ii][jj] = 0.f;
    for (int k = 0; k < 64; k++) {
        float4 bv = *(const float4*)&B[k * 64 + j4];
        float a0 = Arow[(i4 + 0) * 64 + k];
        float a1 = Arow[(i4 + 1) * 64 + k];
        float a2 = Arow[(i4 + 2) * 64 + k];
        float a3 = Arow[(i4 + 3) * 64 + k];
        a[0][0] += a0 * bv.x; a[0][1] += a0 * bv.y; a[0][2] += a0 * bv.z; a[0][3] += a0 * bv.w;
        a[1][0] += a1 * bv.x; a[1][1] += a1 * bv.y; a[1][2] += a1 * bv.z; a[1][3] += a1 * bv.w;
        a[2][0] += a2 * bv.x; a[2][1] += a2 * bv.y; a[2][2] += a2 * bv.z; a[2][3] += a2 * bv.w;
        a[3][0] += a3 * bv.x; a[3][1] += a3 * bv.y; a[3][2] += a3 * bv.z; a[3][3] += a3 * bv.w;
    }
}

// =========================================================================
// FUSED mid-stage: grid (8, NCH+1), 256 threads, 48KB dynamic smem.
// blockIdx.y < NCH: flash partial; == NCH: softmax + Newton-Schulz inverse.
// =========================================================================
__global__ void __launch_bounds__(256) k_mid() {
    extern __shared__ float sm[];
    const int b = blockIdx.x;
    const int t = threadIdx.x;

    if (blockIdx.y == NCH) {
        float* sV = sm;
        float* sA = sm + 4096;
        float* sT = sm + 8192;
        const int j4 = (t & 15) * 4;
        const int i4 = (t >> 4) * 4;

        // S = qlm @ klm^T
        const float* qb = g_qlm + b * LMK * DH;
        const float* kb = g_klm + b * LMK * DH;
        float a[4][4];
#pragma unroll
        for (int ii = 0; ii < 4; ii++)
#pragma unroll
            for (int jj = 0; jj < 4; jj++) a[ii][jj] = 0.f;
        for (int d4 = 0; d4 < DH; d4 += 4) {
            float4 kv[4];
#pragma unroll
            for (int jj = 0; jj < 4; jj++)
                kv[jj] = *(const float4*)(kb + (j4 + jj) * DH + d4);
#pragma unroll
            for (int ii = 0; ii < 4; ii++) {
                float4 qv = *(const float4*)(qb + (i4 + ii) * DH + d4);
#pragma unroll
                for (int jj = 0; jj < 4; jj++)
                    a[ii][jj] += qv.x*kv[jj].x + qv.y*kv[jj].y + qv.z*kv[jj].z + qv.w*kv[jj].w;
            }
        }
#pragma unroll
        for (int ii = 0; ii < 4; ii++)
#pragma unroll
            for (int jj = 0; jj < 4; jj++) sA[(i4 + ii) * 64 + j4 + jj] = a[ii][jj];
        __syncthreads();
        // row softmax: 8 warps x 8 rows
        const int sw = t >> 5;
        const int slane = t & 31;
        for (int rr = 0; rr < 8; rr++) {
            int r = sw * 8 + rr;
            float v0 = sA[r * 64 + slane], v1 = sA[r * 64 + 32 + slane];
            float m = fmaxf(v0, v1);
            for (int o = 16; o; o >>= 1) m = fmaxf(m, __shfl_xor_sync(0xffffffffu, m, o));
            v0 = __expf(v0 - m); v1 = __expf(v1 - m);
            float s = v0 + v1;
            for (int o = 16; o; o >>= 1) s += __shfl_xor_sync(0xffffffffu, s, o);
            float inv = 1.f / s;
            sA[r * 64 + slane] = v0 * inv;
            sA[r * 64 + 32 + slane] = v1 * inv;
        }
        __syncthreads();
        float* Kg = g_k2 + b * 4096;
        for (int e = t; e < 4096; e += 256) Kg[e] = sA[e];
        if (t < 64) {
            float csum = 0.f;
            for (int i = 0; i < 64; i++) csum += sA[i * 64 + t];
            sT[t] = csum;
        }
        __syncthreads();
        if (t == 0) {
            float m = sT[0];
            for (int j = 1; j < 64; j++) m = fmaxf(m, sT[j]);
            sT[0] = m;
        }
        __syncthreads();
        float rdenom = 1.f / sT[0];
        __syncthreads();
        for (int e = t; e < 4096; e += 256) {
            int i = e >> 6, j = e & 63;
            sV[e] = sA[j * 64 + i] * rdenom;
        }
        __syncthreads();

        for (int it = 0; it < 6; it++) {
            mm64(Kg, sV, i4, j4, a);
#pragma unroll
            for (int ii = 0; ii < 4; ii++)
#pragma unroll
                for (int jj = 0; jj < 4; jj++) sA[(i4 + ii) * 64 + j4 + jj] = a[ii][jj];
            __syncthreads();
            mm64(sA, sA, i4, j4, a);
#pragma unroll
            for (int ii = 0; ii < 4; ii++)
#pragma unroll
                for (int jj = 0; jj < 4; jj++)
                    sT[(i4 + ii) * 64 + j4 + jj] = 7.f * sA[(i4 + ii) * 64 + j4 + jj] - a[ii][jj];
            __syncthreads();
            mm64(sA, sT, i4, j4, a);
#pragma unroll
            for (int ii = 0; ii < 4; ii++)
#pragma unroll
                for (int jj = 0; jj < 4; jj++)
                    a[ii][jj] = 15.f * sA[(i4 + ii) * 64 + j4 + jj] - a[ii][jj];
            __syncthreads();
#pragma unroll
            for (int ii = 0; ii < 4; ii++)
#pragma unroll
                for (int jj = 0; jj < 4; jj++) sT[(i4 + ii) * 64 + j4 + jj] = a[ii][jj];
            __syncthreads();
            mm64(sV, sT, i4, j4, a);
#pragma unroll
            for (int ii = 0; ii < 4; ii++)
#pragma unroll
                for (int jj = 0; jj < 4; jj++)
                    a[ii][jj] = 0.25f * (13.f * sV[(i4 + ii) * 64 + j4 + jj] - a[ii][jj]);
            __syncthreads();
#pragma unroll
            for (int ii = 0; ii < 4; ii++)
#pragma unroll
                for (int jj = 0; jj < 4; jj++) sV[(i4 + ii) * 64 + j4 + jj] = a[ii][jj];
            __syncthreads();
        }
        for (int e = t; e < 4096; e += 256) g_kinv[b * 4096 + e] = sV[e];
        return;
    }

    // ---------------- flash partial path (chunk c = blockIdx.y) ------------
    float* sQ   = sm;
    float* sS   = sm + 8192;
    float* sM   = sm + 10240;
    float* sZ   = sm + 10304;
    float* sFac = sm + 10368;
    const int c = blockIdx.y;
    for (int e = t; e < LMK * DH; e += 256) sQ[e] = g_qlm[b * LMK * DH + e];
    if (t < 64) { sM[t] = -1e30f; sZ[t] = 0.f; }
    __syncthreads();

    float acc[32];
#pragma unroll
    for (int i = 0; i < 32; i++) acc[i] = 0.f;
    const int d = t & 127;
    const int hf = t >> 7;
    const int jkey = t & 31;
    const int wl = (t >> 5) * 8;
    const float* kb = g_k + ((long)b * SEQL + c * 128) * DH;
    const float* vb = g_v + ((long)b * SEQL + c * 128) * DH;

    for (int tt = 0; tt < 4; tt++) {
        float s[8];
#pragma unroll
        for (int r = 0; r < 8; r++) s[r] = 0.f;
        const float* krow = kb + (tt * 32 + jkey) * DH;
        for (int d4 = 0; d4 < DH; d4 += 4) {
            float4 kv = *(const float4*)(krow + d4);
#pragma unroll
            for (int r = 0; r < 8; r++) {
                float4 qv = *(const float4*)&sQ[(wl + r) * DH + d4];
                s[r] += qv.x*kv.x + qv.y*kv.y + qv.z*kv.z + qv.w*kv.w;
            }
        }
        __syncthreads();
#pragma unroll
        for (int r = 0; r < 8; r++) {
            int l = wl + r;
            float mt = s[r];
            for (int o = 16; o; o >>= 1) mt = fmaxf(mt, __shfl_xor_sync(0xffffffffu, mt, o));
            float mold = sM[l];
            float mnew = fmaxf(mold, mt);
            float p = __expf(s[r] - mnew);
            float ps = p;
            for (int o = 16; o; o >>= 1) ps += __shfl_xor_sync(0xffffffffu, ps, o);
            if (jkey == 0) {
                float fac = __expf(mold - mnew);
                sFac[l] = fac;
                sZ[l] = sZ[l] * fac + ps;
                sM[l] = mnew;
            }
            sS[l * 32 + jkey] = p;
        }
        __syncthreads();
        const float* vt = vb + tt * 32 * DH;
#pragma unroll
        for (int la = 0; la < 32; la++) acc[la] *= sFac[hf * 32 + la];
        for (int k4 = 0; k4 < 32; k4 += 4) {
            float v0 = vt[(k4 + 0) * DH + d];
            float v1 = vt[(k4 + 1) * DH + d];
            float v2 = vt[(k4 + 2) * DH + d];
            float v3 = vt[(k4 + 3) * DH + d];
#pragma unroll
            for (int la = 0; la < 32; la++) {
                float4 pv = *(float4*)&sS[(hf * 32 + la) * 32 + k4];
                acc[la] += pv.x * v0 + pv.y * v1 + pv.z * v2 + pv.w * v3;
            }
        }
    }
    long base = ((long)(b * NCH + c) * LMK) * DH;
#pragma unroll
    for (int la = 0; la < 32; la++)
        g_ps[base + (hf * 32 + la) * DH + d] = acc[la];
    if (t < 64) {
        g_pm[(b * NCH + c) * LMK + t] = sM[t];
        g_pz[(b * NCH + c) * LMK + t] = sZ[t];
    }
}

// =========================================================================
// combine partials -> F, then G = kinv @ F. 8 blocks x 256 threads.
// =========================================================================
__global__ void __launch_bounds__(256) k_combine() {
    __shared__ float sWt[NCH * LMK];
    __shared__ float sF[LMK * DH];
    const int b = blockIdx.x, t = threadIdx.x;
    if (t < 64) {
        int l = t;
        float M = -1e30f;
        for (int c = 0; c < NCH; c++) M = fmaxf(M, g_pm[(b * NCH + c) * LMK + l]);
        float Z = 0.f;
        for (int c = 0; c < NCH; c++)
            Z += g_pz[(b * NCH + c) * LMK + l] * __expf(g_pm[(b * NCH + c) * LMK + l] - M);
        float rZ = 1.f / Z;
        for (int c = 0; c < NCH; c++)
            sWt[c * LMK + l] = __expf(g_pm[(b * NCH + c) * LMK + l] - M) * rZ;
    }
    __syncthreads();
    const int d = t & 127;
    const int hf = t >> 7;
    for (int la = 0; la < 32; la++) {
        int l = hf * 32 + la;
        float acc = 0.f;
        for (int c = 0; c < NCH; c++)
            acc += g_ps[(((long)(b * NCH + c)) * LMK + l) * DH + d] * sWt[c * LMK + l];
        sF[l * DH + d] = acc;
    }
    __syncthreads();
    const float* inv = g_kinv + b * 4096;
    for (int la = 0; la < 32; la++) {
        int l = hf * 32 + la;
        float acc = 0.f;
        for (int j = 0; j < 64; j++) acc += inv[l * 64 + j] * sF[j * DH + d];
        g_G[((long)b * LMK + l) * DH + d] = acc;
    }
}

// =========================================================================
// fused epilogue: kernel_1 softmax -> @G -> proj -> +bias -> +v residual.
// =========================================================================
__global__ void __launch_bounds__(256) k_out(const float* __restrict__ pb,
                                             float* __restrict__ out) {
    __shared__ float sQ[LMK * DH];
    __shared__ float sP[LMK * LMK];
    const int bid = blockIdx.x;
    const int b = bid >> 7;
    const int n0 = (bid & 127) * 64;
    const int t = threadIdx.x;
    const long rowbase = (long)b * SEQL + n0;

    for (int e = t; e < LMK * DH; e += 256) sQ[e] = g_q[rowbase * DH + e];
    __syncthreads();
    const int sl = t & 63;
    const int rg = t >> 6;
    const float* krow = g_klm + ((long)b * LMK + sl) * DH;
    float s[16];
#pragma unroll
    for (int r = 0; r < 16; r++) s[r] = 0.f;
    for (int d4 = 0; d4 < DH; d4 += 4) {
        float4 kv = *(const float4*)(krow + d4);
#pragma unroll
        for (int r = 0; r < 16; r++) {
            float4 qv = *(const float4*)&sQ[(rg * 16 + r) * DH + d4];
            s[r] += qv.x*kv.x + qv.y*kv.y + qv.z*kv.z + qv.w*kv.w;
        }
    }
#pragma unroll
    for (int r = 0; r < 16; r++) sP[(rg * 16 + r) * 64 + sl] = s[r];
    __syncthreads();
    const int sw = t >> 5;
    const int slane = t & 31;
    for (int rr = 0; rr < 8; rr++) {
        int r = sw * 8 + rr;
        float v0 = sP[r * 64 + slane], v1 = sP[r * 64 + 32 + slane];
        float m = fmaxf(v0, v1);
        for (int o = 16; o; o >>= 1) m = fmaxf(m, __shfl_xor_sync(0xffffffffu, m, o));
        v0 = __expf(v0 - m); v1 = __expf(v1 - m);
        float ssum = v0 + v1;
        for (int o = 16; o; o >>= 1) ssum += __shfl_xor_sync(0xffffffffu, ssum, o);
        float inv = 1.f / ssum;
        sP[r * 64 + slane] = v0 * inv;
        sP[r * 64 + 32 + slane] = v1 * inv;
    }
    __syncthreads();
    const int d = t & 127;
    const int hf = t >> 7;
    float o[32];
#pragma unroll
    for (int la = 0; la < 32; la++) o[la] = 0.f;
    const float* Gb = g_G + (long)b * LMK * DH;
    for (int l4 = 0; l4 < 64; l4 += 4) {
        float g0 = Gb[(l4 + 0) * DH + d];
        float g1 = Gb[(l4 + 1) * DH + d];
        float g2 = Gb[(l4 + 2) * DH + d];
        float g3 = Gb[(l4 + 3) * DH + d];
#pragma unroll
        for (int la = 0; la < 32; la++) {
            float4 pv = *(float4*)&sP[(hf * 32 + la) * 64 + l4];
            o[la] += pv.x * g0 + pv.y * g1 + pv.z * g2 + pv.w * g3;
        }
    }
    __syncthreads();
#pragma unroll
    for (int la = 0; la < 32; la++) sQ[(hf * 32 + la) * DH + d] = o[la];
    __syncthreads();
    float y[32];
#pragma unroll
    for (int la = 0; la < 32; la++) y[la] = 0.f;
    for (int e4 = 0; e4 < DH; e4 += 4) {
        float w0 = g_pwT[(e4 + 0) * DH + d];
        float w1 = g_pwT[(e4 + 1) * DH + d];
        float w2 = g_pwT[(e4 + 2) * DH + d];
        float w3 = g_pwT[(e4 + 3) * DH + d];
#pragma unroll
        for (int la = 0; la < 32; la++) {
            float4 ov = *(float4*)&sQ[(hf * 32 + la) * DH + e4];
            y[la] += ov.x * w0 + ov.y * w1 + ov.z * w2 + ov.w * w3;
        }
    }
    const float bias = pb[d];
#pragma unroll
    for (int la = 0; la < 32; la++) {
        long n = rowbase + hf * 32 + la;
        out[n * DH + d] = g_v[n * DH + d] + y[la] + bias;
    }
}

// ---------------- mma.sync helpers (header-independent u32) ---------------
__device__ __forceinline__ void ldsm4(u32& r0, u32& r1, u32& r2, u32& r3, u32 addr) {
    asm volatile("ldmatrix.sync.aligned.m8n8.x4.shared.b16 {%0,%1,%2,%3}, [%4];" : "=r"(r0), "=r"(r1), "=r"(r2), "=r"(r3) : "r"(addr));
}
__device__ __forceinline__ void mma16816(float* d, const u32* a, const u32* b) {
    asm volatile("mma.sync.aligned.m16n8k16.row.col.f32.bf16.bf16.f32 {%0,%1,%2,%3}, {%4,%5,%6,%7}, {%8,%9}, {%0,%1,%2,%3};" : "+f"(d[0]), "+f"(d[1]), "+f"(d[2]), "+f"(d[3]) : "r"(a[0]), "r"(a[1]), "r"(a[2]), "r"(a[3]), "r"(b[0]), "r"(b[1]));
}
__device__ __forceinline__ u32 pk2(__nv_bfloat16 a, __nv_bfloat16 b) {
    return (u32)__bfloat16_as_ushort(a) | ((u32)__bfloat16_as_ushort(b) << 16);
}
__device__ __forceinline__ void bsplit(float v, __nv_bfloat16& h, __nv_bfloat16& l) {
    h = __float2bfloat16(v);
    l = __float2bfloat16(v - __bfloat162float(h));
}

// =========================================================================
// convert f32 -> (hi,lo) bf16 global buffers. which: 0 = x, 1 = qkv_w.
// grid-stride over float4s.
// =========================================================================
__global__ void __launch_bounds__(256) k_cvt(const float* __restrict__ src,
                                             int n4, int which) {
    __nv_bfloat16* dh = which ? g_wh : g_xh;
    __nv_bfloat16* dl = which ? g_wl : g_xl;
    int i = blockIdx.x * 256 + threadIdx.x;
    if (i >= n4) return;
    float4 v = ((const float4*)src)[i];
    __nv_bfloat16 h0, h1, h2, h3, l0, l1, l2, l3;
    bsplit(v.x, h0, l0);
    bsplit(v.y, h1, l1);
    bsplit(v.z, h2, l2);
    bsplit(v.w, h3, l3);
    ((uint2*)dh)[i] = make_uint2(pk2(h0, h1), pk2(h2, h3));
    ((uint2*)dl)[i] = make_uint2(pk2(l0, l1), pk2(l2, l3));
}

// =========================================================================
// qkv = x @ qkv_w^T via bf16-split tensor-core mma (hh + hl + lh).
// grid (512, 3), 512 thr = 16 warps (4x4), warp tile 32x32, BK=16.
// Operands pre-split in global bf16; staging = pure uint4 copy with
// register prefetch overlapping next-tile LDG under current-tile mma.
// =========================================================================
__global__ void __launch_bounds__(512) k_qkv(const float* __restrict__ x,
                                             const float* __restrict__ w) {
    __shared__ __align__(16) __nv_bfloat16 Ah[128 * SKEW];
    __shared__ __align__(16) __nv_bfloat16 Al[128 * SKEW];
    __shared__ __align__(16) __nv_bfloat16 Bh[128 * SKEW];
    __shared__ __align__(16) __nv_bfloat16 Bl[128 * SKEW];

    const int tid = threadIdx.x;
    const int wid = tid >> 5;
    const int lane = tid & 31;
    const long row0 = (long)blockIdx.x * 128;
    const int sec = blockIdx.y;
    const int wrow0 = sec * 128;
    const int wm = (wid >> 2) * 32;
    const int wn = (wid & 3) * 32;

    // staging map: threads 0-255 stage A (x rows), 256-511 stage B (w rows).
    const int sarr = tid >> 8;
    const int st = tid & 255;
    const int srow2 = st >> 1;
    const int sh8 = (st & 1) * 8;
    const __nv_bfloat16* gH = sarr ? (g_wh + (long)(wrow0 + srow2) * CDIM + sh8)
                                   : (g_xh + (row0 + srow2) * CDIM + sh8);
    const __nv_bfloat16* gL = sarr ? (g_wl + (long)(wrow0 + srow2) * CDIM + sh8)
                                   : (g_xl + (row0 + srow2) * CDIM + sh8);
    __nv_bfloat16* sH = (sarr ? Bh : Ah) + srow2 * SKEW + sh8;
    __nv_bfloat16* sL = (sarr ? Bl : Al) + srow2 * SKEW + sh8;

    float acc[2][4][4];
#pragma unroll
    for (int i = 0; i < 2; i++)
#pragma unroll
        for (int j = 0; j < 4; j++)
#pragma unroll
            for (int e = 0; e < 4; e++) acc[i][j][e] = 0.f;

    const u32 baseAh = (u32)__cvta_generic_to_shared(Ah);
    const u32 baseAl = (u32)__cvta_generic_to_shared(Al);
    const u32 baseBh = (u32)__cvta_generic_to_shared(Bh);
    const u32 baseBl = (u32)__cvta_generic_to_shared(Bl);
    const int arow = (lane & 7) + ((lane >> 3) & 1) * 8;
    const int acol = (lane >> 4) * 8;
    const int bmm = lane >> 3;
    const int brow = (bmm >> 1) * 8 + (lane & 7);
    const int bcol = (bmm & 1) * 8;

    // prefetch tile kt=0
    uint4 ph = *(const uint4*)(gH);
    uint4 pl = *(const uint4*)(gL);

    for (int kt = 0; kt < CDIM; kt += 16) {
        *(uint4*)sH = ph;
        *(uint4*)sL = pl;
        __syncthreads();
        if (kt + 16 < CDIM) {
            ph = *(const uint4*)(gH + kt + 16);
            pl = *(const uint4*)(gL + kt + 16);
        }

        u32 ah[2][4];
        u32 al[2][4];
        u32 bh[4][2];
        u32 bl[4][2];
#pragma unroll
        for (int mt = 0; mt < 2; mt++) {
            u32 ao = (u32)((wm + mt * 16 + arow) * SKEW + acol) * 2u;
            ldsm4(ah[mt][0], ah[mt][1], ah[mt][2], ah[mt][3], baseAh + ao);
            ldsm4(al[mt][0], al[mt][1], al[mt][2], al[mt][3], baseAl + ao);
        }
#pragma unroll
        for (int p = 0; p < 2; p++) {
            u32 bo = (u32)((wn + p * 16 + brow) * SKEW + bcol) * 2u;
            ldsm4(bh[p * 2][0], bh[p * 2][1], bh[p * 2 + 1][0], bh[p * 2 + 1][1], baseBh + bo);
            ldsm4(bl[p * 2][0], bl[p * 2][1], bl[p * 2 + 1][0], bl[p * 2 + 1][1], baseBl + bo);
        }
#pragma unroll
        for (int mt = 0; mt < 2; mt++)
#pragma unroll
            for (int nt = 0; nt < 4; nt++) {
                mma16816(acc[mt][nt], ah[mt], bh[nt]);
                mma16816(acc[mt][nt], ah[mt], bl[nt]);
                mma16816(acc[mt][nt], al[mt], bh[nt]);
            }
        __syncthreads();
    }

    float* dst = sec == 0 ? g_q : (sec == 1 ? g_k : g_v);
    const float scale = sec == 0 ? RSCALE : 1.0f;
    const int grp = lane >> 2;
    const int qd = lane & 3;
#pragma unroll
    for (int mt = 0; mt < 2; mt++)
#pragma unroll
        for (int nt = 0; nt < 4; nt++) {
            long m0 = row0 + wm + mt * 16 + grp;
            int col = wn + nt * 8 + qd * 2;
            *(float2*)&dst[m0 * DH + col] = make_float2(acc[mt][nt][0] * scale, acc[mt][nt][1] * scale);
            *(float2*)&dst[(m0 + 8) * DH + col] = make_float2(acc[mt][nt][2] * scale, acc[mt][nt][3] * scale);
        }
}

// =========================================================================
extern "C" void kernel_launch(void* const* d_in, const int* in_sizes, int n_in,
                              void* d_out, int out_size) {
    const float* x      = (const float*)d_in[0];
    const float* qkv_w  = (const float*)d_in[1];
    const float* proj_w = (const float*)d_in[2];
    const float* proj_b = (const float*)d_in[3];
    float* out = (float*)d_out;

    const int xn4 = NB * SEQL * CDIM / 4;       // 6291456
    const int wn4 = 3 * DH * CDIM / 4;          // 36864
    k_cvt<<<(xn4 + 255) / 256, 256>>>(x, xn4, 0);
    k_cvt<<<(wn4 + 255) / 256, 256>>>(qkv_w, wn4, 1);
    k_qkv<<<dim3(512, 3), 512>>>(x, qkv_w);
    k_lm<<<512, 128>>>();
    k_pwT<<<128, 128>>>(proj_w);
    k_mid<<<dim3(8, NCH + 1), 256, 49152>>>();
    k_combine<<<8, 256>>>();
    k_out<<<1024, 256>>>(proj_b, out);
}